// round 1
// baseline (speedup 1.0000x reference)
#include <cuda_runtime.h>
#include <math.h>

// Problem constants (fixed by reference)
#define Bn 2
#define Cn 64
#define C8n 8
#define Nn 9216            // H*W = 96*96
#define TOTELEM (Bn*Cn*Nn) // 1,179,648

// Scratch (allocation-free rule: __device__ globals)
__device__ float g_q[Bn * Nn * C8n];   // [b][n][o]
__device__ float g_k[Bn * C8n * Nn];   // [b][o][n]
__device__ float g_v[Bn * Cn * Nn];    // [b][c][n]

// ---------------------------------------------------------------------------
// Kernel 1: 1x1-conv projections q,k,v. One thread per (b,n).
// ---------------------------------------------------------------------------
__global__ void __launch_bounds__(128) proj_kernel(
    const float* __restrict__ x,
    const float* __restrict__ Wq, const float* __restrict__ bq,
    const float* __restrict__ Wk, const float* __restrict__ bk,
    const float* __restrict__ Wv, const float* __restrict__ bv,
    const float* __restrict__ gamma)
{
    if (*gamma == 0.0f) return;  // fast path: attention output unused

    __shared__ float sWq[C8n * Cn];
    __shared__ float sWk[C8n * Cn];
    __shared__ float sWv[Cn * Cn];
    __shared__ float sbq[C8n], sbk[C8n], sbv[Cn];

    int t = threadIdx.x;
    for (int i = t; i < C8n * Cn; i += blockDim.x) { sWq[i] = Wq[i]; sWk[i] = Wk[i]; }
    for (int i = t; i < Cn * Cn;  i += blockDim.x) { sWv[i] = Wv[i]; }
    if (t < C8n) { sbq[t] = bq[t]; sbk[t] = bk[t]; }
    if (t < Cn)  { sbv[t] = bv[t]; }
    __syncthreads();

    int gid = blockIdx.x * blockDim.x + t;
    if (gid >= Bn * Nn) return;
    int b = gid / Nn;
    int n = gid - b * Nn;
    const float* xb = x + (size_t)b * Cn * Nn;

    float aq[C8n], ak[C8n], av[Cn];
#pragma unroll
    for (int o = 0; o < C8n; o++) { aq[o] = sbq[o]; ak[o] = sbk[o]; }
#pragma unroll
    for (int o = 0; o < Cn; o++)  { av[o] = sbv[o]; }

    for (int c = 0; c < Cn; c++) {
        float xv = xb[(size_t)c * Nn + n];   // coalesced across threads (adjacent n)
#pragma unroll
        for (int o = 0; o < C8n; o++) {
            aq[o] = fmaf(sWq[o * Cn + c], xv, aq[o]);
            ak[o] = fmaf(sWk[o * Cn + c], xv, ak[o]);
        }
#pragma unroll
        for (int o = 0; o < Cn; o++) {
            av[o] = fmaf(sWv[o * Cn + c], xv, av[o]);
        }
    }

#pragma unroll
    for (int o = 0; o < C8n; o++) {
        g_q[(size_t)gid * C8n + o] = aq[o];
        g_k[((size_t)b * C8n + o) * Nn + n] = ak[o];
    }
#pragma unroll
    for (int o = 0; o < Cn; o++) {
        g_v[((size_t)b * Cn + o) * Nn + n] = av[o];
    }
}

// ---------------------------------------------------------------------------
// Kernel 2: per-row fused energy -> softmax -> (attn @ v) -> gamma*out + x.
// One persistent block per attention row i (grid-stride over B*N rows).
// ---------------------------------------------------------------------------
__global__ void __launch_bounds__(256) attn_kernel(
    const float* __restrict__ x,
    const float* __restrict__ gamma,
    const float* __restrict__ dyn,
    float* __restrict__ out)
{
    __shared__ __align__(16) float sE[Nn];  // energy / probs row (36 KB)
    __shared__ float sred[8];

    float g = *gamma;
    if (g == 0.0f) return;  // fast path handled by copy_kernel
    float dy = *dyn;

    int t = threadIdx.x;
    int warp = t >> 5, lane = t & 31;

    for (int row = blockIdx.x; row < Bn * Nn; row += gridDim.x) {
        int b = row / Nn;
        int i = row - b * Nn;

        float q[C8n];
#pragma unroll
        for (int o = 0; o < C8n; o++) q[o] = g_q[(size_t)row * C8n + o];
        const float* kb = g_k + (size_t)b * C8n * Nn;

        // Pass 1: energy + local max
        float lmax = -1e30f;
        for (int m = t; m < Nn; m += 256) {
            float e = 0.0f;
#pragma unroll
            for (int o = 0; o < C8n; o++) e = fmaf(q[o], kb[(size_t)o * Nn + m], e);
            sE[m] = e;
            lmax = fmaxf(lmax, e);
        }
#pragma unroll
        for (int s = 16; s > 0; s >>= 1)
            lmax = fmaxf(lmax, __shfl_xor_sync(0xffffffffu, lmax, s));
        if (lane == 0) sred[warp] = lmax;
        __syncthreads();
        float rmax = sred[0];
#pragma unroll
        for (int w = 1; w < 8; w++) rmax = fmaxf(rmax, sred[w]);

        // Pass 2: exp + local sum
        float lsum = 0.0f;
        for (int m = t; m < Nn; m += 256) {
            float p = __expf(sE[m] - rmax);
            sE[m] = p;
            lsum += p;
        }
#pragma unroll
        for (int s = 16; s > 0; s >>= 1)
            lsum += __shfl_xor_sync(0xffffffffu, lsum, s);
        __syncthreads();                 // all rmax reads + sE writes done
        if (lane == 0) sred[warp] = lsum;
        __syncthreads();
        float rsum = sred[0];
#pragma unroll
        for (int w = 1; w < 8; w++) rsum += sred[w];
        float scale = dy / rsum;

        // Pass 3: out[c,i] = g * scale * sum_m p[m] * v[c,m] + x[c,i]
        // 256 threads = 64 channels x 4 m-groups; float4 streaming of v.
        int c  = t >> 2;
        int gq = t & 3;
        const float4* vrow = (const float4*)(g_v + ((size_t)b * Cn + c) * Nn);
        const float4* pE   = (const float4*)sE;
        float acc = 0.0f;
        for (int m4 = gq; m4 < Nn / 4; m4 += 4) {
            float4 v4 = vrow[m4];
            float4 p4 = pE[m4];
            acc = fmaf(v4.x, p4.x, acc);
            acc = fmaf(v4.y, p4.y, acc);
            acc = fmaf(v4.z, p4.z, acc);
            acc = fmaf(v4.w, p4.w, acc);
        }
        acc += __shfl_down_sync(0xffffffffu, acc, 2);
        acc += __shfl_down_sync(0xffffffffu, acc, 1);
        if (gq == 0) {
            size_t oi = ((size_t)b * Cn + c) * Nn + i;
            out[oi] = fmaf(g * scale, acc, x[oi]);
        }
        __syncthreads();  // protect sE before next row's pass 1
    }
}

// ---------------------------------------------------------------------------
// Kernel 3: gamma == 0 fast path: out = x (bit-exact).
// ---------------------------------------------------------------------------
__global__ void __launch_bounds__(256) copy_kernel(
    const float4* __restrict__ x,
    const float* __restrict__ gamma,
    float4* __restrict__ out)
{
    if (*gamma != 0.0f) return;
    int idx = blockIdx.x * blockDim.x + threadIdx.x;
    if (idx < TOTELEM / 4) out[idx] = x[idx];
}

// ---------------------------------------------------------------------------
extern "C" void kernel_launch(void* const* d_in, const int* in_sizes, int n_in,
                              void* d_out, int out_size)
{
    const float* x     = (const float*)d_in[0];
    const float* Wq    = (const float*)d_in[1];
    const float* bq    = (const float*)d_in[2];
    const float* Wk    = (const float*)d_in[3];
    const float* bk    = (const float*)d_in[4];
    const float* Wv    = (const float*)d_in[5];
    const float* bv    = (const float*)d_in[6];
    const float* gamma = (const float*)d_in[7];
    const float* dyn   = (const float*)d_in[8];
    float* out = (float*)d_out;

    // General path (device-side early exit when gamma == 0)
    proj_kernel<<<(Bn * Nn + 127) / 128, 128>>>(x, Wq, bq, Wk, bk, Wv, bv, gamma);
    attn_kernel<<<888, 256>>>(x, gamma, dyn, out);

    // gamma == 0 path: out = x
    copy_kernel<<<(TOTELEM / 4 + 255) / 256, 256>>>(
        (const float4*)x, gamma, (float4*)out);
}